// round 3
// baseline (speedup 1.0000x reference)
#include <cuda_runtime.h>
#include <cstdint>

#define N_NODES 8192
#define K_IN    512
#define F_OUT   64
#define NEG_SLOPE 0.01f

// ---------------- scratch ----------------
__device__ __align__(16) float g_Z[N_NODES * F_OUT];
__device__ float g_zi[N_NODES];
__device__ float g_zj[N_NODES];
__device__ float g_S[F_OUT];

// ---------------- kernel 1: fused GEMM + row-dots + col-sums ----------------
// tile: 32 rows x 64 cols, 256 threads, 2x4 micro-tile, grid = 256 blocks
__global__ __launch_bounds__(256) void gemm_fused_kernel(
    const float* __restrict__ X, const float* __restrict__ W,
    const float* __restrict__ bias,
    const float* __restrict__ a1, const float* __restrict__ a2)
{
    __shared__ __align__(16) float As[32][68];   // [row][k]
    __shared__ __align__(16) float Bs[64][68];   // [k][out]
    __shared__ __align__(16) float cs[F_OUT];

    const int tid  = threadIdx.x;
    const int tx   = tid & 15;     // 4 cols each
    const int ty   = tid >> 4;     // 2 rows each
    const int row0 = blockIdx.x * 32;

    float acc[2][4] = {};

    for (int k0 = 0; k0 < K_IN; k0 += 64) {
        // load A tile: 32x64 floats = 512 float4, 2 per thread
        #pragma unroll
        for (int q = 0; q < 2; q++) {
            int idx = tid + 256 * q;
            int r   = idx >> 4;
            int kk4 = (idx & 15) << 2;
            *(float4*)&As[r][kk4] =
                *(const float4*)&X[(size_t)(row0 + r) * K_IN + k0 + kk4];
        }
        // load B tile: 64 out x 64 k = 1024 float4, 4 per thread (transpose in smem)
        #pragma unroll
        for (int q = 0; q < 4; q++) {
            int idx = tid + 256 * q;
            int o   = idx >> 4;
            int kk4 = (idx & 15) << 2;
            float4 w = *(const float4*)&W[(size_t)o * K_IN + k0 + kk4];
            Bs[kk4 + 0][o] = w.x;
            Bs[kk4 + 1][o] = w.y;
            Bs[kk4 + 2][o] = w.z;
            Bs[kk4 + 3][o] = w.w;
        }
        __syncthreads();

        #pragma unroll 16
        for (int kk = 0; kk < 64; kk++) {
            float a0  = As[ty * 2 + 0][kk];
            float a1r = As[ty * 2 + 1][kk];
            float4 bv = *(const float4*)&Bs[kk][tx * 4];
            acc[0][0] += a0  * bv.x; acc[0][1] += a0  * bv.y;
            acc[0][2] += a0  * bv.z; acc[0][3] += a0  * bv.w;
            acc[1][0] += a1r * bv.x; acc[1][1] += a1r * bv.y;
            acc[1][2] += a1r * bv.z; acc[1][3] += a1r * bv.w;
        }
        __syncthreads();
    }

    // add bias (scalar loads — alignment-safe)
    #pragma unroll
    for (int v = 0; v < 4; v++) {
        float bb = __ldg(&bias[tx * 4 + v]);
        acc[0][v] += bb;
        acc[1][v] += bb;
    }

    // write Z
    #pragma unroll
    for (int u = 0; u < 2; u++) {
        float4 zo = make_float4(acc[u][0], acc[u][1], acc[u][2], acc[u][3]);
        *(float4*)&g_Z[(size_t)(row0 + ty * 2 + u) * F_OUT + tx * 4] = zo;
    }

    // row dots: zi = sum(a1*z), zj = sum(a2*z), reduce across 16-lane tx groups
    float s1a[2] = {0.f, 0.f}, s2a[2] = {0.f, 0.f};
    #pragma unroll
    for (int v = 0; v < 4; v++) {
        float a1s = __ldg(&a1[tx * 4 + v]);
        float a2s = __ldg(&a2[tx * 4 + v]);
        s1a[0] += a1s * acc[0][v]; s2a[0] += a2s * acc[0][v];
        s1a[1] += a1s * acc[1][v]; s2a[1] += a2s * acc[1][v];
    }
    #pragma unroll
    for (int u = 0; u < 2; u++) {
        float s1 = s1a[u], s2 = s2a[u];
        #pragma unroll
        for (int off = 8; off > 0; off >>= 1) {
            s1 += __shfl_down_sync(0xFFFFFFFFu, s1, off, 16);
            s2 += __shfl_down_sync(0xFFFFFFFFu, s2, off, 16);
        }
        if (tx == 0) {
            g_zi[row0 + ty * 2 + u] = s1;
            g_zj[row0 + ty * 2 + u] = s2;
        }
    }

    // column sums -> g_S (g_S pre-zeroed by memset)
    if (tid < F_OUT) cs[tid] = 0.0f;
    __syncthreads();
    #pragma unroll
    for (int v = 0; v < 4; v++)
        atomicAdd(&cs[tx * 4 + v], acc[0][v] + acc[1][v]);
    __syncthreads();
    if (tid < F_OUT) atomicAdd(&g_S[tid], cs[tid]);
}

// ---------------- kernel 2: stream adj + closed-form softmax combine ----------------
// one block per row; 256 threads
__global__ __launch_bounds__(256) void attn_kernel(
    const float* __restrict__ adj, float* __restrict__ out)
{
    __shared__ __align__(16) float s_red[16][F_OUT];   // first: guaranteed 16B-aligned
    __shared__ int   s_idx[1024];
    __shared__ int   s_cnt;
    __shared__ int   s_diag;

    const int i    = blockIdx.x;
    const int tid  = threadIdx.x;
    const int lane = tid & 31;

    if (tid == 0) { s_cnt = 0; s_diag = 0; }
    __syncthreads();

    // phase 1a: batch all 8 float4 loads (high MLP), streaming hint
    const float4* row = (const float4*)(adj + (size_t)i * N_NODES);
    float4 v[8];
    #pragma unroll
    for (int q = 0; q < 8; q++)
        v[q] = __ldcs(&row[tid + q * 256]);

    // phase 1b: warp-ballot compaction into s_idx
    const unsigned lt = (1u << lane) - 1u;
    #pragma unroll
    for (int q = 0; q < 8; q++) {
        int j = (tid + q * 256) << 2;
        unsigned m0 = __ballot_sync(0xFFFFFFFFu, v[q].x != 0.0f);
        unsigned m1 = __ballot_sync(0xFFFFFFFFu, v[q].y != 0.0f);
        unsigned m2 = __ballot_sync(0xFFFFFFFFu, v[q].z != 0.0f);
        unsigned m3 = __ballot_sync(0xFFFFFFFFu, v[q].w != 0.0f);
        int tot = __popc(m0) + __popc(m1) + __popc(m2) + __popc(m3);
        int base = 0;
        if (lane == 0 && tot) base = atomicAdd(&s_cnt, tot);
        base = __shfl_sync(0xFFFFFFFFu, base, 0);
        if (v[q].x != 0.0f) { s_idx[base + __popc(m0 & lt)] = j;     if (j     == i) s_diag = 1; }
        base += __popc(m0);
        if (v[q].y != 0.0f) { s_idx[base + __popc(m1 & lt)] = j + 1; if (j + 1 == i) s_diag = 1; }
        base += __popc(m1);
        if (v[q].z != 0.0f) { s_idx[base + __popc(m2 & lt)] = j + 2; if (j + 2 == i) s_diag = 1; }
        base += __popc(m2);
        if (v[q].w != 0.0f) { s_idx[base + __popc(m3 & lt)] = j + 3; if (j + 3 == i) s_diag = 1; }
    }
    __syncthreads();

    const int cnt = s_cnt;
    const int dg  = s_diag;

    // phase 2: R_full[o] = sum over neighbors of z[j][o], float4, 16 row-groups
    const int cg = tid >> 4;          // row group 0..15
    const int co = (tid & 15) << 2;   // col offset (x4 floats = 16B)
    float4 acc = make_float4(0.f, 0.f, 0.f, 0.f);
    for (int p = cg; p < cnt; p += 16) {
        float4 t = __ldg((const float4*)&g_Z[(size_t)s_idx[p] * F_OUT + co]);
        acc.x += t.x; acc.y += t.y; acc.z += t.z; acc.w += t.w;
    }
    *(float4*)&s_red[cg][co] = acc;
    __syncthreads();

    // phase 3: closed-form softmax aggregation + residual + relu
    if (tid < F_OUT) {
        float Rfull = 0.0f;
        #pragma unroll
        for (int g = 0; g < 16; g++) Rfull += s_red[g][tid];

        float zio  = g_Z[(size_t)i * F_OUT + tid];
        float Roff = Rfull - (dg ? zio : 0.0f);
        int   koff = cnt - dg;

        float c  = g_zi[i];
        float lc = c > 0.0f ? c : NEG_SLOPE * c;
        float e1 = expf(lc);
        float wd = 1.0f;
        if (dg) {
            float t = c + g_zj[i];
            t = t > 0.0f ? t : NEG_SLOPE * t;
            wd = expf(t);
        }
        float Zden  = (float)koff * e1 + wd + (float)(N_NODES - 1 - koff);
        float numer = (e1 - 1.0f) * Roff + (wd - 1.0f) * zio + g_S[tid];
        float h = zio - numer / Zden;
        out[(size_t)i * F_OUT + tid] = h > 0.0f ? h : 0.0f;
    }
}

// ---------------- launch ----------------
extern "C" void kernel_launch(void* const* d_in, const int* in_sizes, int n_in,
                              void* d_out, int out_size)
{
    const float* X    = (const float*)d_in[0];
    const float* adj  = (const float*)d_in[1];
    // d_in[2] = eye_matrix: identity by construction, never read
    const float* W    = (const float*)d_in[3];
    const float* bias = (const float*)d_in[4];
    const float* a1   = (const float*)d_in[5];
    const float* a2   = (const float*)d_in[6];
    float* out        = (float*)d_out;

    void* sPtr = nullptr;
    cudaGetSymbolAddress(&sPtr, g_S);
    cudaMemsetAsync(sPtr, 0, F_OUT * sizeof(float));

    gemm_fused_kernel<<<N_NODES / 32, 256>>>(X, W, bias, a1, a2);
    attn_kernel<<<N_NODES, 256>>>(adj, out);
}

// round 4
// speedup vs baseline: 1.6630x; 1.6630x over previous
#include <cuda_runtime.h>
#include <cstdint>

#define N_NODES 8192
#define K_IN    512
#define F_OUT   64
#define NEG_SLOPE 0.01f

// ---------------- scratch ----------------
__device__ __align__(16) float g_Z[N_NODES * F_OUT];
__device__ float g_zi[N_NODES];
__device__ float g_zj[N_NODES];
__device__ float g_S[F_OUT];

// ---------------- kernel 1: fused GEMM + row-dots + col-sums ----------------
// tile: 32 rows x 64 cols, 128 threads, 4x4 micro-tile, grid = 256 blocks
__global__ __launch_bounds__(128) void gemm_fused_kernel(
    const float* __restrict__ X, const float* __restrict__ W,
    const float* __restrict__ bias,
    const float* __restrict__ a1, const float* __restrict__ a2)
{
    __shared__ __align__(16) float As[32][68];   // [row][k]
    __shared__ __align__(16) float Bs[64][68];   // [k][out]
    __shared__ __align__(16) float cs[F_OUT];

    const int tid  = threadIdx.x;
    const int tx   = tid & 15;     // col group: 4 cols each
    const int ty   = tid >> 4;     // row group 0..7: 4 rows each
    const int row0 = blockIdx.x * 32;

    float acc[4][4] = {};

    for (int k0 = 0; k0 < K_IN; k0 += 64) {
        // A tile: 32x64 = 512 float4, 4 per thread
        #pragma unroll
        for (int q = 0; q < 4; q++) {
            int idx = tid + 128 * q;
            int r   = idx >> 4;
            int kk4 = (idx & 15) << 2;
            *(float4*)&As[r][kk4] =
                *(const float4*)&X[(size_t)(row0 + r) * K_IN + k0 + kk4];
        }
        // B tile: 64 out x 64 k = 1024 float4, 8 per thread (transpose into smem)
        #pragma unroll
        for (int q = 0; q < 8; q++) {
            int idx = tid + 128 * q;
            int o   = idx >> 4;
            int kk4 = (idx & 15) << 2;
            float4 wv = *(const float4*)&W[(size_t)o * K_IN + k0 + kk4];
            Bs[kk4 + 0][o] = wv.x;
            Bs[kk4 + 1][o] = wv.y;
            Bs[kk4 + 2][o] = wv.z;
            Bs[kk4 + 3][o] = wv.w;
        }
        __syncthreads();

        #pragma unroll 16
        for (int kk = 0; kk < 64; kk++) {
            float a0 = As[ty * 4 + 0][kk];
            float a1r = As[ty * 4 + 1][kk];
            float a2r = As[ty * 4 + 2][kk];
            float a3r = As[ty * 4 + 3][kk];
            float4 bv = *(const float4*)&Bs[kk][tx * 4];
            acc[0][0] += a0  * bv.x; acc[0][1] += a0  * bv.y; acc[0][2] += a0  * bv.z; acc[0][3] += a0  * bv.w;
            acc[1][0] += a1r * bv.x; acc[1][1] += a1r * bv.y; acc[1][2] += a1r * bv.z; acc[1][3] += a1r * bv.w;
            acc[2][0] += a2r * bv.x; acc[2][1] += a2r * bv.y; acc[2][2] += a2r * bv.z; acc[2][3] += a2r * bv.w;
            acc[3][0] += a3r * bv.x; acc[3][1] += a3r * bv.y; acc[3][2] += a3r * bv.z; acc[3][3] += a3r * bv.w;
        }
        __syncthreads();
    }

    // bias
    #pragma unroll
    for (int v = 0; v < 4; v++) {
        float bb = __ldg(&bias[tx * 4 + v]);
        #pragma unroll
        for (int u = 0; u < 4; u++) acc[u][v] += bb;
    }

    // write Z
    #pragma unroll
    for (int u = 0; u < 4; u++) {
        float4 zo = make_float4(acc[u][0], acc[u][1], acc[u][2], acc[u][3]);
        *(float4*)&g_Z[(size_t)(row0 + ty * 4 + u) * F_OUT + tx * 4] = zo;
    }

    // row dots: zi = sum(a1*z), zj = sum(a2*z); 16-lane reductions within half-warps
    #pragma unroll
    for (int u = 0; u < 4; u++) {
        float s1 = 0.f, s2 = 0.f;
        #pragma unroll
        for (int v = 0; v < 4; v++) {
            float a1s = __ldg(&a1[tx * 4 + v]);
            float a2s = __ldg(&a2[tx * 4 + v]);
            s1 += a1s * acc[u][v];
            s2 += a2s * acc[u][v];
        }
        #pragma unroll
        for (int off = 8; off > 0; off >>= 1) {
            s1 += __shfl_down_sync(0xFFFFFFFFu, s1, off, 16);
            s2 += __shfl_down_sync(0xFFFFFFFFu, s2, off, 16);
        }
        if (tx == 0) {
            g_zi[row0 + ty * 4 + u] = s1;
            g_zj[row0 + ty * 4 + u] = s2;
        }
    }

    // column sums -> g_S (pre-zeroed by memset)
    if (tid < F_OUT) cs[tid] = 0.0f;
    __syncthreads();
    #pragma unroll
    for (int v = 0; v < 4; v++)
        atomicAdd(&cs[tx * 4 + v], acc[0][v] + acc[1][v] + acc[2][v] + acc[3][v]);
    __syncthreads();
    if (tid < F_OUT) atomicAdd(&g_S[tid], cs[tid]);
}

// ---------------- kernel 2: stream adj + direct per-warp neighbor accumulation -----
// one block per row; 256 threads = 8 warps, warp accumulates z-rows for its nonzeros
__global__ __launch_bounds__(256) void attn_kernel(
    const float* __restrict__ adj, float* __restrict__ out)
{
    __shared__ __align__(16) float s_red[8][F_OUT];
    __shared__ int s_cnt;
    __shared__ int s_diag;

    const int i    = blockIdx.x;
    const int tid  = threadIdx.x;
    const int w    = tid >> 5;
    const int lane = tid & 31;

    if (tid == 0) { s_cnt = 0; s_diag = 0; }
    __syncthreads();

    const float4* row = (const float4*)(adj + (size_t)i * N_NODES);

    float2 racc = make_float2(0.f, 0.f);
    int cntw = 0;
    int dgw  = 0;

    float4 v = __ldcs(&row[tid]);    // prefetch q=0
    #pragma unroll
    for (int q = 0; q < 8; q++) {
        float4 cur = v;
        if (q < 7) v = __ldcs(&row[tid + (q + 1) * 256]);   // prefetch next

        unsigned m0 = __ballot_sync(0xFFFFFFFFu, cur.x != 0.0f);
        unsigned m1 = __ballot_sync(0xFFFFFFFFu, cur.y != 0.0f);
        unsigned m2 = __ballot_sync(0xFFFFFFFFu, cur.z != 0.0f);
        unsigned m3 = __ballot_sync(0xFFFFFFFFu, cur.w != 0.0f);
        cntw += __popc(m0) + __popc(m1) + __popc(m2) + __popc(m3);

        const int jbase = (q * 256 + w * 32) << 2;
        unsigned mm[4] = {m0, m1, m2, m3};
        #pragma unroll
        for (int c = 0; c < 4; c++) {
            unsigned mc = mm[c];
            while (mc) {                         // uniform across warp
                int b = __ffs(mc) - 1;
                mc &= mc - 1;
                int j = jbase + (b << 2) + c;
                if (j == i) dgw = 1;
                // all 32 lanes cooperatively load z[j] (64 floats, float2/lane)
                float2 t = *(const float2*)&g_Z[(size_t)j * F_OUT + lane * 2];
                racc.x += t.x;
                racc.y += t.y;
            }
        }
    }

    s_red[w][lane * 2]     = racc.x;
    s_red[w][lane * 2 + 1] = racc.y;
    if (lane == 0) {
        if (cntw) atomicAdd(&s_cnt, cntw);
        if (dgw)  s_diag = 1;                    // benign: only ever writes 1
    }
    __syncthreads();

    // closed-form softmax aggregation + residual + relu
    if (tid < F_OUT) {
        float Rfull = 0.0f;
        #pragma unroll
        for (int g = 0; g < 8; g++) Rfull += s_red[g][tid];

        const int cnt = s_cnt;
        const int dg  = s_diag;

        float zio  = g_Z[(size_t)i * F_OUT + tid];
        float Roff = Rfull - (dg ? zio : 0.0f);
        int   koff = cnt - dg;

        float c  = g_zi[i];
        float lc = c > 0.0f ? c : NEG_SLOPE * c;
        float e1 = expf(lc);
        float wd = 1.0f;
        if (dg) {
            float t = c + g_zj[i];
            t = t > 0.0f ? t : NEG_SLOPE * t;
            wd = expf(t);
        }
        float Zden  = (float)koff * e1 + wd + (float)(N_NODES - 1 - koff);
        float numer = (e1 - 1.0f) * Roff + (wd - 1.0f) * zio + g_S[tid];
        float h = zio - numer / Zden;
        out[(size_t)i * F_OUT + tid] = h > 0.0f ? h : 0.0f;
    }
}

// ---------------- launch ----------------
extern "C" void kernel_launch(void* const* d_in, const int* in_sizes, int n_in,
                              void* d_out, int out_size)
{
    const float* X    = (const float*)d_in[0];
    const float* adj  = (const float*)d_in[1];
    // d_in[2] = eye_matrix: identity by construction, never read
    const float* W    = (const float*)d_in[3];
    const float* bias = (const float*)d_in[4];
    const float* a1   = (const float*)d_in[5];
    const float* a2   = (const float*)d_in[6];
    float* out        = (float*)d_out;

    void* sPtr = nullptr;
    cudaGetSymbolAddress(&sPtr, g_S);
    cudaMemsetAsync(sPtr, 0, F_OUT * sizeof(float));

    gemm_fused_kernel<<<N_NODES / 32, 128>>>(X, W, bias, a1, a2);
    attn_kernel<<<N_NODES, 256>>>(adj, out);
}